// round 1
// baseline (speedup 1.0000x reference)
#include <cuda_runtime.h>

// Problem constants
#define BZ 4
#define DD 768
#define LL 4096
#define MM (BZ * LL)  // 16384 rows

// Scratch: 3 x 48MB static device buffers (allowed: no runtime alloc)
__device__ float g_a[MM * DD];  // Xr -> B2 -> enc
__device__ float g_u[MM * DD];  // U
__device__ float g_p[MM * DD];  // P -> Q

// ---------------------------------------------------------------------------
// Kernel 1: transpose x [B, D, L] -> Xr [B*L, D]
// ---------------------------------------------------------------------------
__global__ void transpose_x_kernel(const float* __restrict__ x, float* __restrict__ xr) {
    __shared__ float tile[32][33];
    int b = blockIdx.z;
    int t0 = blockIdx.x * 32;
    int d0 = blockIdx.y * 32;
    int tx = threadIdx.x;
    // read x[b, d0+i, t0+tx] coalesced along t
    #pragma unroll
    for (int i = threadIdx.y; i < 32; i += 8)
        tile[tx][i] = x[(size_t)(b * DD + d0 + i) * LL + t0 + tx];
    __syncthreads();
    // write xr[(b*L + t0+i), d0+tx] coalesced along d
    #pragma unroll
    for (int i = threadIdx.y; i < 32; i += 8)
        xr[(size_t)(b * LL + t0 + i) * DD + d0 + tx] = tile[i][tx];
}

// ---------------------------------------------------------------------------
// Kernel 2: GEMM  C[M,N] = op(A)[M,K] @ W[N,K]^T  (+ bias1[n]+bias2[n])
// op(A) = relu(A) if RELU_A. M=16384, N=K=768. BM=BN=128, BK=16, 256 thr, 8x8/thr.
// ---------------------------------------------------------------------------
template <bool RELU_A, bool ADD_BIAS>
__global__ __launch_bounds__(256) void gemm_nt_kernel(
    const float* __restrict__ A, const float* __restrict__ W,
    const float* __restrict__ bias1, const float* __restrict__ bias2,
    float* __restrict__ C) {
    const int K = DD, N = DD;
    const int BM = 128, BN = 128, BK = 16;

    __shared__ __align__(16) float As[2][BK][BM];
    __shared__ __align__(16) float Bs[2][BK][BN];

    int tid = threadIdx.x;
    int m0 = blockIdx.y * BM;
    int n0 = blockIdx.x * BN;
    int tr = tid / 16;         // 0..15
    int tc = tid % 16;         // 0..15
    int lrow = tid / 4;        // 0..63
    int lcol = (tid % 4) * 4;  // 0,4,8,12

    float acc[8][8] = {};

    // prologue: load k-tile 0 into buffer 0
    {
        #pragma unroll
        for (int h = 0; h < 2; ++h) {
            int r = lrow + h * 64;
            float4 va = *(const float4*)(A + (size_t)(m0 + r) * K + lcol);
            if (RELU_A) {
                va.x = fmaxf(va.x, 0.f); va.y = fmaxf(va.y, 0.f);
                va.z = fmaxf(va.z, 0.f); va.w = fmaxf(va.w, 0.f);
            }
            As[0][lcol + 0][r] = va.x; As[0][lcol + 1][r] = va.y;
            As[0][lcol + 2][r] = va.z; As[0][lcol + 3][r] = va.w;
            float4 vb = *(const float4*)(W + (size_t)(n0 + r) * K + lcol);
            Bs[0][lcol + 0][r] = vb.x; Bs[0][lcol + 1][r] = vb.y;
            Bs[0][lcol + 2][r] = vb.z; Bs[0][lcol + 3][r] = vb.w;
        }
    }
    __syncthreads();

    const int NK = K / BK;  // 48
    int buf = 0;
    float4 pa[2], pb[2];

    for (int kt = 0; kt < NK; ++kt) {
        bool has_next = (kt + 1 < NK);
        if (has_next) {
            int k0 = (kt + 1) * BK;
            #pragma unroll
            for (int h = 0; h < 2; ++h) {
                int r = lrow + h * 64;
                pa[h] = *(const float4*)(A + (size_t)(m0 + r) * K + k0 + lcol);
                pb[h] = *(const float4*)(W + (size_t)(n0 + r) * K + k0 + lcol);
            }
        }
        // compute on current buffer
        #pragma unroll
        for (int k = 0; k < BK; ++k) {
            float4 a0 = *(const float4*)&As[buf][k][tr * 8];
            float4 a1 = *(const float4*)&As[buf][k][tr * 8 + 4];
            float4 b0 = *(const float4*)&Bs[buf][k][tc * 8];
            float4 b1 = *(const float4*)&Bs[buf][k][tc * 8 + 4];
            float ra[8] = {a0.x, a0.y, a0.z, a0.w, a1.x, a1.y, a1.z, a1.w};
            float rb[8] = {b0.x, b0.y, b0.z, b0.w, b1.x, b1.y, b1.z, b1.w};
            #pragma unroll
            for (int i = 0; i < 8; ++i)
                #pragma unroll
                for (int j = 0; j < 8; ++j)
                    acc[i][j] += ra[i] * rb[j];
        }
        if (has_next) {
            int nb = buf ^ 1;
            #pragma unroll
            for (int h = 0; h < 2; ++h) {
                int r = lrow + h * 64;
                float4 va = pa[h];
                if (RELU_A) {
                    va.x = fmaxf(va.x, 0.f); va.y = fmaxf(va.y, 0.f);
                    va.z = fmaxf(va.z, 0.f); va.w = fmaxf(va.w, 0.f);
                }
                As[nb][lcol + 0][r] = va.x; As[nb][lcol + 1][r] = va.y;
                As[nb][lcol + 2][r] = va.z; As[nb][lcol + 3][r] = va.w;
                Bs[nb][lcol + 0][r] = pb[h].x; Bs[nb][lcol + 1][r] = pb[h].y;
                Bs[nb][lcol + 2][r] = pb[h].z; Bs[nb][lcol + 3][r] = pb[h].w;
            }
            __syncthreads();
            buf = nb;
        }
    }

    // epilogue
    #pragma unroll
    for (int i = 0; i < 8; ++i) {
        int m = m0 + tr * 8 + i;
        float* cp = C + (size_t)m * N + n0 + tc * 8;
        #pragma unroll
        for (int j = 0; j < 8; j += 4) {
            float4 v;
            v.x = acc[i][j + 0]; v.y = acc[i][j + 1];
            v.z = acc[i][j + 2]; v.w = acc[i][j + 3];
            if (ADD_BIAS) {
                int n = n0 + tc * 8 + j;
                v.x += bias1[n + 0] + bias2[n + 0];
                v.y += bias1[n + 1] + bias2[n + 1];
                v.z += bias1[n + 2] + bias2[n + 2];
                v.w += bias1[n + 3] + bias2[n + 3];
            }
            *(float4*)(cp + j) = v;
        }
    }
}

// ---------------------------------------------------------------------------
// Kernel 3: O[r] = relu(U[r] + (t>0 ? P[r-1] : 0)),  t = r % L
// ---------------------------------------------------------------------------
__global__ void shift_relu_kernel(const float* __restrict__ U, const float* __restrict__ P,
                                  float* __restrict__ O) {
    int idx = blockIdx.x * blockDim.x + threadIdx.x;  // float4 index
    const int total4 = MM * DD / 4;
    if (idx >= total4) return;
    int e = idx * 4;
    int r = e / DD;
    int t = r & (LL - 1);
    float4 u = *(const float4*)(U + e);
    float4 p = make_float4(0.f, 0.f, 0.f, 0.f);
    if (t > 0) p = *(const float4*)(P + e - DD);
    float4 o;
    o.x = fmaxf(u.x + p.x, 0.f); o.y = fmaxf(u.y + p.y, 0.f);
    o.z = fmaxf(u.z + p.z, 0.f); o.w = fmaxf(u.w + p.w, 0.f);
    *(float4*)(O + e) = o;
}

// ---------------------------------------------------------------------------
// Kernel 4: C3 = relu(U + shift(Q)); write transposed -> enc [B, D, L]
// ---------------------------------------------------------------------------
__global__ void c3_transpose_kernel(const float* __restrict__ U, const float* __restrict__ Q,
                                    float* __restrict__ enc) {
    __shared__ float tile[32][33];  // [t_local][d_local]
    int b = blockIdx.z;
    int t0 = blockIdx.x * 32;
    int d0 = blockIdx.y * 32;
    int tx = threadIdx.x;
    #pragma unroll
    for (int i = threadIdx.y; i < 32; i += 8) {
        int t = t0 + i;
        int r = b * LL + t;
        float u = U[(size_t)r * DD + d0 + tx];
        float q = (t > 0) ? Q[(size_t)(r - 1) * DD + d0 + tx] : 0.f;
        tile[i][tx] = fmaxf(u + q, 0.f);
    }
    __syncthreads();
    #pragma unroll
    for (int i = threadIdx.y; i < 32; i += 8)
        enc[(size_t)(b * DD + d0 + i) * LL + t0 + tx] = tile[tx][i];
}

// ---------------------------------------------------------------------------
// Kernel 5: z = enc + x; LayerNorm over L per (b,d) row; out [B, D, L]
// ---------------------------------------------------------------------------
__global__ __launch_bounds__(256) void layernorm_kernel(
    const float* __restrict__ enc, const float* __restrict__ x,
    const float* __restrict__ gamma, const float* __restrict__ beta,
    float* __restrict__ out) {
    __shared__ float zbuf[LL];
    __shared__ float red[256];
    int row = blockIdx.x;  // b*D + d
    int tid = threadIdx.x;
    const float* e = enc + (size_t)row * LL;
    const float* xx = x + (size_t)row * LL;
    float* op = out + (size_t)row * LL;

    float s = 0.f;
    for (int t = tid; t < LL; t += 256) {
        float z = e[t] + xx[t];
        zbuf[t] = z;
        s += z;
    }
    red[tid] = s;
    __syncthreads();
    #pragma unroll
    for (int o = 128; o > 0; o >>= 1) {
        if (tid < o) red[tid] += red[tid + o];
        __syncthreads();
    }
    float mean = red[0] * (1.f / LL);
    __syncthreads();

    float v = 0.f;
    for (int t = tid; t < LL; t += 256) {
        float d = zbuf[t] - mean;
        v += d * d;
    }
    red[tid] = v;
    __syncthreads();
    #pragma unroll
    for (int o = 128; o > 0; o >>= 1) {
        if (tid < o) red[tid] += red[tid + o];
        __syncthreads();
    }
    float rstd = rsqrtf(red[0] * (1.f / LL) + 1e-12f);

    for (int t = tid; t < LL; t += 256)
        op[t] = (zbuf[t] - mean) * rstd * gamma[t] + beta[t];
}

// ---------------------------------------------------------------------------
// Launch
// ---------------------------------------------------------------------------
extern "C" void kernel_launch(void* const* d_in, const int* in_sizes, int n_in,
                              void* d_out, int out_size) {
    const float* x = (const float*)d_in[0];
    const float* W_ih = (const float*)d_in[1];
    const float* W_hh = (const float*)d_in[2];
    const float* b_ih = (const float*)d_in[3];
    const float* b_hh = (const float*)d_in[4];
    const float* gamma = (const float*)d_in[5];
    const float* beta = (const float*)d_in[6];
    float* out = (float*)d_out;

    float *pa, *pu, *pp;
    cudaGetSymbolAddress((void**)&pa, g_a);
    cudaGetSymbolAddress((void**)&pu, g_u);
    cudaGetSymbolAddress((void**)&pp, g_p);

    dim3 tgrid(LL / 32, DD / 32, BZ), tblk(32, 8);
    dim3 ggrid(DD / 128, MM / 128);

    // 1. Xr = transpose(x)                          -> g_a
    transpose_x_kernel<<<tgrid, tblk>>>(x, pa);
    // 2. U = Xr @ W_ih^T + (b_ih + b_hh)            -> g_u
    gemm_nt_kernel<false, true><<<ggrid, 256>>>(pa, W_ih, b_ih, b_hh, pu);
    // 3. P = relu(U) @ W_hh^T                       -> g_p
    gemm_nt_kernel<true, false><<<ggrid, 256>>>(pu, W_hh, nullptr, nullptr, pp);
    // 4. B2 = relu(U + shift(P))                    -> g_a
    {
        int total4 = MM * DD / 4;
        shift_relu_kernel<<<(total4 + 255) / 256, 256>>>(pu, pp, pa);
    }
    // 5. Q = B2 @ W_hh^T                            -> g_p
    gemm_nt_kernel<false, false><<<ggrid, 256>>>(pa, W_hh, nullptr, nullptr, pp);
    // 6. enc = transpose(relu(U + shift(Q)))        -> g_a  [B, D, L]
    c3_transpose_kernel<<<tgrid, tblk>>>(pu, pp, pa);
    // 7. out = LayerNorm_L(enc + x) * gamma + beta
    layernorm_kernel<<<BZ * DD, 256>>>(pa, x, gamma, beta, out);
}

// round 8
// speedup vs baseline: 2.0746x; 2.0746x over previous
#include <cuda_runtime.h>
#include <cuda_fp16.h>
#include <cstdint>

#define BZ 4
#define DD 768
#define LL 4096
#define MM (BZ * LL)   // 16384
#define KW 2304        // split-K GEMM depth (3 x 768)
#define KA 1536        // compact A3 width: [Ah | Al]
#define NKC 72         // 2304 / 32 k-chunks
#define BKC 32
#define AS_STRIDE 40   // padded halfs per smem row
#define STAGE_BYTES (128 * AS_STRIDE * 2)  // 10240
#define NSTAGE 3
#define SM_TOTAL (NSTAGE * 2 * STAGE_BYTES)  // 61440

// Scratch (static device memory; no runtime alloc)
__device__ __align__(16) float g_u[MM * DD];        // U (fp32)
__device__ __align__(16) float g_p[MM * DD];        // P / Q (fp32)
__device__ __align__(16) float g_big[MM * DD];      // A3 (half MM x 1536) OR enc (fp32) - 48MB
__device__ __align__(16) __half g_wih3[DD * KW];    // W_ih split [Bh|Bl|Bh]
__device__ __align__(16) __half g_whh3[DD * KW];    // W_hh split

// ---------------------------------------------------------------------------
// PTX helpers (all plain sm_80-era ISA: valid on virtual compute_103)
// ---------------------------------------------------------------------------
__device__ __forceinline__ uint32_t smem_u32(const void* p) {
    uint32_t a;
    asm("{ .reg .u64 t; cvta.to.shared.u64 t, %1; cvt.u32.u64 %0, t; }" : "=r"(a) : "l"(p));
    return a;
}
__device__ __forceinline__ void cp_async16(uint32_t saddr, const void* gaddr) {
    asm volatile("cp.async.ca.shared.global [%0], [%1], 16;" :: "r"(saddr), "l"(gaddr));
}
__device__ __forceinline__ void cp_commit() {
    asm volatile("cp.async.commit_group;");
}
__device__ __forceinline__ void cp_wait1() {
    asm volatile("cp.async.wait_group 1;");
}
__device__ __forceinline__ void ldm_x4(uint32_t& r0, uint32_t& r1, uint32_t& r2, uint32_t& r3,
                                       uint32_t addr) {
    asm volatile("ldmatrix.sync.aligned.m8n8.x4.shared.b16 {%0,%1,%2,%3}, [%4];"
                 : "=r"(r0), "=r"(r1), "=r"(r2), "=r"(r3) : "r"(addr));
}
__device__ __forceinline__ void mma16816(float* c, const uint32_t* a, const uint32_t* b) {
    asm volatile(
        "mma.sync.aligned.m16n8k16.row.col.f32.f16.f16.f32 "
        "{%0,%1,%2,%3}, {%4,%5,%6,%7}, {%8,%9}, {%0,%1,%2,%3};"
        : "+f"(c[0]), "+f"(c[1]), "+f"(c[2]), "+f"(c[3])
        : "r"(a[0]), "r"(a[1]), "r"(a[2]), "r"(a[3]), "r"(b[0]), "r"(b[1]));
}

// ---------------------------------------------------------------------------
// HMMA GEMM: C[M,768] = A3[M, split-K 2304] @ W3[768,2304]^T (+ bias1+bias2)
// BM=BN=128, BK=32, 8 warps (4x2), warp tile 32x64, 3-stage cp.async.
// k-chunk i source in compact A3: i<24 -> Ah, 24<=i<48 -> Ah, i>=48 -> Al.
// ---------------------------------------------------------------------------
template <bool ADD_BIAS>
__global__ __launch_bounds__(256) void gemm_hmma(
    const __half* __restrict__ A3, const __half* __restrict__ B3,
    const float* __restrict__ bias1, const float* __restrict__ bias2,
    float* __restrict__ C) {
    extern __shared__ __align__(16) unsigned char smem[];
    const uint32_t sa_base = smem_u32(smem);                       // A stages
    const uint32_t sb_base = sa_base + NSTAGE * STAGE_BYTES;       // B stages

    const int tid = threadIdx.x;
    const int wid = tid >> 5, lane = tid & 31;
    const int m0 = blockIdx.y * 128, n0 = blockIdx.x * 128;
    const int warp_m = (wid >> 1) * 32;   // 0,32,64,96
    const int warp_n = (wid & 1) * 64;    // 0,64

    // cp.async source/dest coords for this thread (2 chunks of 16B per tile)
    const int cr0 = tid >> 2, cc0 = (tid & 3) * 8;        // p = tid
    const int cr1 = (tid + 256) >> 2;                     // p = tid + 256 (same cc)

    float acc[2][8][4] = {};

    // ldmatrix per-lane address components
    const int a_row = warp_m + (lane & 7) + ((lane >> 3) & 1) * 8;  // + mt*16
    const int a_colh = (lane >> 4) * 8;                              // + ks*16
    const int b_row = warp_n + (lane & 7) + (lane >> 4) * 8;         // + j*16
    const int b_colh = ((lane >> 3) & 1) * 8;                        // + ks*16

    auto load_stage = [&](int chunk, int stage) {
        const int srcA = (chunk < 24) ? chunk * BKC
                       : (chunk < 48) ? (chunk - 24) * BKC
                                      : 768 + (chunk - 48) * BKC;
        const int kb = chunk * BKC;
        const uint32_t sa = sa_base + stage * STAGE_BYTES;
        const uint32_t sb = sb_base + stage * STAGE_BYTES;
        cp_async16(sa + (cr0 * AS_STRIDE + cc0) * 2, A3 + (size_t)(m0 + cr0) * KA + srcA + cc0);
        cp_async16(sa + (cr1 * AS_STRIDE + cc0) * 2, A3 + (size_t)(m0 + cr1) * KA + srcA + cc0);
        cp_async16(sb + (cr0 * AS_STRIDE + cc0) * 2, B3 + (size_t)(n0 + cr0) * KW + kb + cc0);
        cp_async16(sb + (cr1 * AS_STRIDE + cc0) * 2, B3 + (size_t)(n0 + cr1) * KW + kb + cc0);
    };

    // prologue: stages 0,1
    load_stage(0, 0); cp_commit();
    load_stage(1, 1); cp_commit();

    for (int i = 0; i < NKC; ++i) {
        cp_wait1();
        __syncthreads();
        if (i + 2 < NKC) load_stage(i + 2, (i + 2) % NSTAGE);
        cp_commit();

        const int st = i % NSTAGE;
        const uint32_t a_st = sa_base + st * STAGE_BYTES;
        const uint32_t b_st = sb_base + st * STAGE_BYTES;

        #pragma unroll
        for (int ks = 0; ks < 2; ++ks) {
            uint32_t af[2][4], bf[8][2];
            #pragma unroll
            for (int mt = 0; mt < 2; ++mt)
                ldm_x4(af[mt][0], af[mt][1], af[mt][2], af[mt][3],
                       a_st + ((a_row + mt * 16) * AS_STRIDE + a_colh + ks * 16) * 2);
            #pragma unroll
            for (int j = 0; j < 4; ++j)
                ldm_x4(bf[2 * j][0], bf[2 * j][1], bf[2 * j + 1][0], bf[2 * j + 1][1],
                       b_st + ((b_row + j * 16) * AS_STRIDE + b_colh + ks * 16) * 2);
            #pragma unroll
            for (int mt = 0; mt < 2; ++mt)
                #pragma unroll
                for (int nt = 0; nt < 8; ++nt)
                    mma16816(acc[mt][nt], af[mt], bf[nt]);
        }
    }

    // epilogue
    #pragma unroll
    for (int mt = 0; mt < 2; ++mt) {
        #pragma unroll
        for (int h = 0; h < 2; ++h) {
            const int row = m0 + warp_m + mt * 16 + (lane >> 2) + h * 8;
            float* cp = C + (size_t)row * DD + n0 + warp_n + (lane & 3) * 2;
            #pragma unroll
            for (int nt = 0; nt < 8; ++nt) {
                float2 v;
                v.x = acc[mt][nt][h * 2 + 0];
                v.y = acc[mt][nt][h * 2 + 1];
                if (ADD_BIAS) {
                    const int n = n0 + warp_n + nt * 8 + (lane & 3) * 2;
                    v.x += bias1[n + 0] + bias2[n + 0];
                    v.y += bias1[n + 1] + bias2[n + 1];
                }
                *(float2*)(cp + nt * 8) = v;
            }
        }
    }
}

// ---------------------------------------------------------------------------
// Split helpers
// ---------------------------------------------------------------------------
__device__ __forceinline__ void split_h(float v, __half& h, __half& l) {
    h = __float2half_rn(v);
    l = __float2half_rn(v - __half2float(h));
}

// W [768,768] fp32 -> W3 [768,2304] = [Bh | Bl | Bh]
__global__ void conv_w_kernel(const float* __restrict__ W, __half* __restrict__ W3) {
    int idx = blockIdx.x * 256 + threadIdx.x;
    if (idx >= DD * DD) return;
    int r = idx / DD, k = idx % DD;
    __half h, l;
    split_h(W[idx], h, l);
    size_t base = (size_t)r * KW;
    W3[base + k] = h;
    W3[base + DD + k] = l;
    W3[base + 2 * DD + k] = h;
}

// x [B,D,L] fp32 -> X3 [B*L, 1536] half = [hi | lo] (transpose + split)
__global__ void conv_x_kernel(const float* __restrict__ x, __half* __restrict__ X3) {
    __shared__ float tile[32][33];
    int b = blockIdx.z, t0 = blockIdx.x * 32, d0 = blockIdx.y * 32;
    int tx = threadIdx.x;
    #pragma unroll
    for (int i = threadIdx.y; i < 32; i += 8)
        tile[tx][i] = x[(size_t)(b * DD + d0 + i) * LL + t0 + tx];
    __syncthreads();
    #pragma unroll
    for (int i = threadIdx.y; i < 32; i += 8) {
        __half h, l;
        split_h(tile[i][tx], h, l);
        size_t row = (size_t)(b * LL + t0 + i) * KA;
        X3[row + d0 + tx] = h;
        X3[row + DD + d0 + tx] = l;
    }
}

// A3 = split(relu(U))
__global__ void conv_relu_kernel(const float* __restrict__ U, __half* __restrict__ A3) {
    int idx = blockIdx.x * 256 + threadIdx.x;
    int e = idx * 4;
    if (e >= MM * DD) return;
    int r = e / DD, c = e % DD;
    float4 u = *(const float4*)(U + e);
    float v[4] = {fmaxf(u.x, 0.f), fmaxf(u.y, 0.f), fmaxf(u.z, 0.f), fmaxf(u.w, 0.f)};
    __half h[4], l[4];
    #pragma unroll
    for (int j = 0; j < 4; ++j) split_h(v[j], h[j], l[j]);
    size_t base = (size_t)r * KA + c;
    *(uint2*)(A3 + base) = *(const uint2*)h;
    *(uint2*)(A3 + base + DD) = *(const uint2*)l;
}

// A3 = split(relu(U + shift(P)))
__global__ void conv_shift_kernel(const float* __restrict__ U, const float* __restrict__ P,
                                  __half* __restrict__ A3) {
    int idx = blockIdx.x * 256 + threadIdx.x;
    int e = idx * 4;
    if (e >= MM * DD) return;
    int r = e / DD, c = e % DD;
    int t = r & (LL - 1);
    float4 u = *(const float4*)(U + e);
    float4 p = make_float4(0.f, 0.f, 0.f, 0.f);
    if (t > 0) p = *(const float4*)(P + e - DD);
    float v[4] = {fmaxf(u.x + p.x, 0.f), fmaxf(u.y + p.y, 0.f),
                  fmaxf(u.z + p.z, 0.f), fmaxf(u.w + p.w, 0.f)};
    __half h[4], l[4];
    #pragma unroll
    for (int j = 0; j < 4; ++j) split_h(v[j], h[j], l[j]);
    size_t base = (size_t)r * KA + c;
    *(uint2*)(A3 + base) = *(const uint2*)h;
    *(uint2*)(A3 + base + DD) = *(const uint2*)l;
}

// enc = transpose(relu(U + shift(Q))) -> [B, D, L] fp32
__global__ void c3_transpose_kernel(const float* __restrict__ U, const float* __restrict__ Q,
                                    float* __restrict__ enc) {
    __shared__ float tile[32][33];
    int b = blockIdx.z, t0 = blockIdx.x * 32, d0 = blockIdx.y * 32;
    int tx = threadIdx.x;
    #pragma unroll
    for (int i = threadIdx.y; i < 32; i += 8) {
        int t = t0 + i;
        int r = b * LL + t;
        float u = U[(size_t)r * DD + d0 + tx];
        float q = (t > 0) ? Q[(size_t)(r - 1) * DD + d0 + tx] : 0.f;
        tile[i][tx] = fmaxf(u + q, 0.f);
    }
    __syncthreads();
    #pragma unroll
    for (int i = threadIdx.y; i < 32; i += 8)
        enc[(size_t)(b * DD + d0 + i) * LL + t0 + tx] = tile[tx][i];
}

// LayerNorm over L per (b,d) row
__global__ __launch_bounds__(256) void layernorm_kernel(
    const float* __restrict__ enc, const float* __restrict__ x,
    const float* __restrict__ gamma, const float* __restrict__ beta,
    float* __restrict__ out) {
    __shared__ float zbuf[LL];
    __shared__ float red[256];
    int row = blockIdx.x;
    int tid = threadIdx.x;
    const float* e = enc + (size_t)row * LL;
    const float* xx = x + (size_t)row * LL;
    float* op = out + (size_t)row * LL;

    float s = 0.f;
    for (int t = tid; t < LL; t += 256) {
        float z = e[t] + xx[t];
        zbuf[t] = z;
        s += z;
    }
    red[tid] = s;
    __syncthreads();
    #pragma unroll
    for (int o = 128; o > 0; o >>= 1) {
        if (tid < o) red[tid] += red[tid + o];
        __syncthreads();
    }
    float mean = red[0] * (1.f / LL);
    __syncthreads();

    float v = 0.f;
    for (int t = tid; t < LL; t += 256) {
        float d = zbuf[t] - mean;
        v += d * d;
    }
    red[tid] = v;
    __syncthreads();
    #pragma unroll
    for (int o = 128; o > 0; o >>= 1) {
        if (tid < o) red[tid] += red[tid + o];
        __syncthreads();
    }
    float rstd = rsqrtf(red[0] * (1.f / LL) + 1e-12f);

    for (int t = tid; t < LL; t += 256)
        op[t] = (zbuf[t] - mean) * rstd * gamma[t] + beta[t];
}

// ---------------------------------------------------------------------------
// Launch
// ---------------------------------------------------------------------------
extern "C" void kernel_launch(void* const* d_in, const int* in_sizes, int n_in,
                              void* d_out, int out_size) {
    const float* x = (const float*)d_in[0];
    const float* W_ih = (const float*)d_in[1];
    const float* W_hh = (const float*)d_in[2];
    const float* b_ih = (const float*)d_in[3];
    const float* b_hh = (const float*)d_in[4];
    const float* gamma = (const float*)d_in[5];
    const float* beta = (const float*)d_in[6];
    float* out = (float*)d_out;

    float *pu, *pp, *pbig;
    __half *pwih3, *pwhh3;
    cudaGetSymbolAddress((void**)&pu, g_u);
    cudaGetSymbolAddress((void**)&pp, g_p);
    cudaGetSymbolAddress((void**)&pbig, g_big);
    cudaGetSymbolAddress((void**)&pwih3, g_wih3);
    cudaGetSymbolAddress((void**)&pwhh3, g_whh3);
    __half* pa3 = (__half*)pbig;

    cudaFuncSetAttribute(gemm_hmma<true>, cudaFuncAttributeMaxDynamicSharedMemorySize, SM_TOTAL);
    cudaFuncSetAttribute(gemm_hmma<false>, cudaFuncAttributeMaxDynamicSharedMemorySize, SM_TOTAL);

    dim3 tgrid(LL / 32, DD / 32, BZ), tblk(32, 8);
    dim3 ggrid(DD / 128, MM / 128);  // (6, 128)
    const int ew_blocks = (MM * DD / 4 + 255) / 256;

    // W splits
    conv_w_kernel<<<(DD * DD + 255) / 256, 256>>>(W_ih, pwih3);
    conv_w_kernel<<<(DD * DD + 255) / 256, 256>>>(W_hh, pwhh3);
    // A3 = split(transpose(x))
    conv_x_kernel<<<tgrid, tblk>>>(x, pa3);
    // U = X @ W_ih^T + b_ih + b_hh
    gemm_hmma<true><<<ggrid, 256, SM_TOTAL>>>(pa3, pwih3, b_ih, b_hh, pu);
    // A3 = split(relu(U))
    conv_relu_kernel<<<ew_blocks, 256>>>(pu, pa3);
    // P = relu(U) @ W_hh^T
    gemm_hmma<false><<<ggrid, 256, SM_TOTAL>>>(pa3, pwhh3, nullptr, nullptr, pp);
    // A3 = split(relu(U + shift(P)))
    conv_shift_kernel<<<ew_blocks, 256>>>(pu, pp, pa3);
    // Q = B2 @ W_hh^T
    gemm_hmma<false><<<ggrid, 256, SM_TOTAL>>>(pa3, pwhh3, nullptr, nullptr, pp);
    // enc = transpose(relu(U + shift(Q)))
    c3_transpose_kernel<<<tgrid, tblk>>>(pu, pp, pbig);
    // out = LayerNorm_L(enc + x)
    layernorm_kernel<<<BZ * DD, 256>>>(pbig, x, gamma, beta, out);
}